// round 3
// baseline (speedup 1.0000x reference)
#include <cuda_runtime.h>

// DistMult edge score: out[e] = sum_d node[src[e]][d] * rel[e][d] * node[dst[e]][d]
// N_NODES=100000, N_EDGES=600000, DIM=128.
//
// Indices: reference declares int64, but JAX default (no x64) coerces randint
// to int32 — we read int32. Defensive clamp converts any dtype-model error
// into a visible rel_err instead of an illegal-access fault.
//
// One warp per edge; lane l handles float4 at column 4*l (32 lanes * 4 = 128).
// All three row reads are fully coalesced (512B/warp/array).
// rel_emb is streamed exactly once -> __ldcs (evict-first) so the 51MB node
// table stays resident in L2 (~126MB) and the 1.2M random node gathers mostly
// hit L2 instead of HBM.

#define DIM 128

__global__ __launch_bounds__(256)
void distmult_kernel(const float* __restrict__ node_emb,
                     const float* __restrict__ rel_emb,
                     const int* __restrict__ src,
                     const int* __restrict__ dst,
                     float* __restrict__ out,
                     int n_edges,
                     int n_nodes) {
    int gwarp = (blockIdx.x * blockDim.x + threadIdx.x) >> 5;
    int lane  = threadIdx.x & 31;
    if (gwarp >= n_edges) return;

    int s = src[gwarp];
    int d = dst[gwarp];
    // defensive clamp: never fault; dtype bugs surface as rel_err
    s = min(max(s, 0), n_nodes - 1);
    d = min(max(d, 0), n_nodes - 1);

    const float4* __restrict__ h = reinterpret_cast<const float4*>(node_emb + (long long)s * DIM);
    const float4* __restrict__ t = reinterpret_cast<const float4*>(node_emb + (long long)d * DIM);
    const float4* __restrict__ r = reinterpret_cast<const float4*>(rel_emb + (long long)gwarp * DIM);

    float4 hv = h[lane];
    float4 tv = t[lane];
    float4 rv = __ldcs(r + lane);   // streaming: evict-first, keep node table in L2

    float acc = hv.x * rv.x * tv.x
              + hv.y * rv.y * tv.y
              + hv.z * rv.z * tv.z
              + hv.w * rv.w * tv.w;

    // warp tree reduction
    #pragma unroll
    for (int off = 16; off > 0; off >>= 1)
        acc += __shfl_xor_sync(0xffffffffu, acc, off);

    if (lane == 0)
        out[gwarp] = acc;
}

extern "C" void kernel_launch(void* const* d_in, const int* in_sizes, int n_in,
                              void* d_out, int out_size) {
    const float* node_emb = (const float*)d_in[0];
    const float* rel_emb  = (const float*)d_in[1];
    const int*   src      = (const int*)d_in[2];
    const int*   dst      = (const int*)d_in[3];
    float* out = (float*)d_out;

    int n_edges = in_sizes[1] / DIM;   // rel_emb is [E, 128] -> robust E
    int n_nodes = in_sizes[0] / DIM;   // node_emb is [N, 128]

    int threads = 256;                 // 8 warps/block -> 8 edges/block
    int blocks  = (n_edges + 7) / 8;

    distmult_kernel<<<blocks, threads>>>(node_emb, rel_emb, src, dst, out,
                                         n_edges, n_nodes);
}

// round 4
// speedup vs baseline: 1.3179x; 1.3179x over previous
#include <cuda_runtime.h>

// DistMult edge score: out[e] = sum_d node[src[e]][d] * rel[e][d] * node[dst[e]][d]
// N_NODES=100000, N_EDGES=600000, DIM=128, int32 indices (confirmed R3).
//
// R3 finding: bytes moved (369MB) match the model but DRAM only 48% busy,
// issue 33% -> latency-bound. Fix: 4 edges per warp, all 12 float4 loads
// issued before any use (MLP ~12/thread vs 3/thread in R3).
//
// Lane l owns float4 at column 4*l. All row reads coalesced (512B/warp).
// rel_emb streamed once -> __ldcs keeps the 51MB node table resident in L2.

#define DIM 128
#define EPW 4   // edges per warp

__global__ __launch_bounds__(256)
void distmult_kernel(const float* __restrict__ node_emb,
                     const float* __restrict__ rel_emb,
                     const int* __restrict__ src,
                     const int* __restrict__ dst,
                     float* __restrict__ out,
                     int n_edges,
                     int n_nodes) {
    int warp = (blockIdx.x * blockDim.x + threadIdx.x) >> 5;
    int lane = threadIdx.x & 31;
    long long ebase = (long long)warp * EPW;
    if (ebase >= n_edges) return;

    // Index loads (uniform across warp -> broadcast, L1/L2 hit).
    int s[EPW], d[EPW];
    #pragma unroll
    for (int i = 0; i < EPW; i++) {
        long long e = ebase + i;
        if (e >= n_edges) e = n_edges - 1;        // tail guard (600000 % 4 == 0 anyway)
        int si = src[e], di = dst[e];
        s[i] = min(max(si, 0), n_nodes - 1);       // defensive clamp
        d[i] = min(max(di, 0), n_nodes - 1);
    }

    // Front-batched vector loads: 12 independent float4 LDGs in flight.
    float4 hv[EPW], tv[EPW], rv[EPW];
    #pragma unroll
    for (int i = 0; i < EPW; i++) {
        const float4* h = reinterpret_cast<const float4*>(node_emb + (long long)s[i] * DIM);
        const float4* t = reinterpret_cast<const float4*>(node_emb + (long long)d[i] * DIM);
        const float4* r = reinterpret_cast<const float4*>(rel_emb + (ebase + i) * DIM);
        hv[i] = h[lane];
        tv[i] = t[lane];
        rv[i] = __ldcs(r + lane);   // streaming: evict-first
    }

    // Per-edge partial dot products.
    float acc[EPW];
    #pragma unroll
    for (int i = 0; i < EPW; i++) {
        acc[i] = hv[i].x * rv[i].x * tv[i].x
               + hv[i].y * rv[i].y * tv[i].y
               + hv[i].z * rv[i].z * tv[i].z
               + hv[i].w * rv[i].w * tv[i].w;
    }

    // 4 independent butterfly reductions, interleaved to pipeline SHFL latency.
    #pragma unroll
    for (int off = 16; off > 0; off >>= 1) {
        #pragma unroll
        for (int i = 0; i < EPW; i++)
            acc[i] += __shfl_xor_sync(0xffffffffu, acc[i], off);
    }

    if (lane < EPW) {
        long long e = ebase + lane;
        if (e < n_edges)
            out[e] = acc[lane];     // acc[i] is uniform post-reduction; lane i stores edge i
    }
}

extern "C" void kernel_launch(void* const* d_in, const int* in_sizes, int n_in,
                              void* d_out, int out_size) {
    const float* node_emb = (const float*)d_in[0];
    const float* rel_emb  = (const float*)d_in[1];
    const int*   src      = (const int*)d_in[2];
    const int*   dst      = (const int*)d_in[3];
    float* out = (float*)d_out;

    int n_edges = in_sizes[1] / DIM;   // rel_emb [E,128]
    int n_nodes = in_sizes[0] / DIM;   // node_emb [N,128]

    int threads = 256;                             // 8 warps -> 32 edges per block
    int edges_per_block = (threads / 32) * EPW;
    int blocks = (n_edges + edges_per_block - 1) / edges_per_block;

    distmult_kernel<<<blocks, threads>>>(node_emb, rel_emb, src, dst, out,
                                         n_edges, n_nodes);
}